// round 1
// baseline (speedup 1.0000x reference)
#include <cuda_runtime.h>
#include <cuda_bf16.h>

// PathRaster2d: quadratic Bezier (3 control points) rasterized on 2048x2048.
// Strategy: 128x8 tiles. 32 curve samples computed per block (cheap, broadcast
// from L1). Exact per-tile point-to-box distance early-out -> almost every tile
// writes float4 zeros (pure STG, DRAM-bound ~3us). Active tiles (~handful) run
// the full 32-sample min-distance loop with reference-matched fp32 rounding.

#define CANVAS_H 2048
#define CANVAS_W 2048
#define NSAMP 32
#define TILE_W 128
#define TILE_H 8

__global__ void __launch_bounds__(256)
path_raster_kernel(const float* __restrict__ kp, float* __restrict__ out)
{
    __shared__ float sy[NSAMP];
    __shared__ float sx[NSAMP];
    __shared__ int s_active;

    const int tx = threadIdx.x;          // 0..31
    const int ty = threadIdx.y;          // 0..7
    const int tid = ty * 32 + tx;
    const int x0 = blockIdx.x * TILE_W;
    const int y0 = blockIdx.y * TILE_H;

    if (tid == 0) s_active = 0;
    __syncthreads();

    if (tid < NSAMP) {
        // t_i = i * fl(1/31), endpoint forced to 1.0 (matches jnp.linspace)
        float t = (tid == NSAMP - 1) ? 1.0f : (float)tid * (1.0f / (float)(NSAMP - 1));
        float u = __fsub_rn(1.0f, t);
        // Bernstein basis, reference op order: u*u, (2*t)*u, t*t
        float b0 = __fmul_rn(u, u);
        float b1 = __fmul_rn(__fmul_rn(2.0f, t), u);
        float b2 = __fmul_rn(t, t);
        // key_points * [H, W] : exact (power-of-2 scale)
        float ky0 = __fmul_rn(kp[0], 2048.0f), kx0 = __fmul_rn(kp[1], 2048.0f);
        float ky1 = __fmul_rn(kp[2], 2048.0f), kx1 = __fmul_rn(kp[3], 2048.0f);
        float ky2 = __fmul_rn(kp[4], 2048.0f), kx2 = __fmul_rn(kp[5], 2048.0f);
        // basis @ kp : plain mul/add, left-to-right (no fma contraction)
        float py = __fadd_rn(__fadd_rn(__fmul_rn(b0, ky0), __fmul_rn(b1, ky1)),
                             __fmul_rn(b2, ky2));
        float px = __fadd_rn(__fadd_rn(__fmul_rn(b0, kx0), __fmul_rn(b1, kx1)),
                             __fmul_rn(b2, kx2));
        sy[tid] = py;
        sx[tid] = px;
        // Exact point-to-tile-box distance; activity threshold padded to 4.5
        // (safety vs rounding; only ever adds tiles, never changes output).
        float bdy = fmaxf(fmaxf((float)y0 - py, py - (float)(y0 + TILE_H - 1)), 0.0f);
        float bdx = fmaxf(fmaxf((float)x0 - px, px - (float)(x0 + TILE_W - 1)), 0.0f);
        if (bdy * bdy + bdx * bdx < 4.5f) s_active = 1;
    }
    __syncthreads();

    const int x = x0 + tx * 4;
    const int y = y0 + ty;
    float4 v;

    if (!s_active) {
        v = make_float4(0.0f, 0.0f, 0.0f, 0.0f);
    } else {
        const float fy = (float)y;
        const float fx0 = (float)x;
        const float fx1 = fx0 + 1.0f;
        const float fx2 = fx0 + 2.0f;
        const float fx3 = fx0 + 3.0f;
        float m0 = 3.4e38f, m1 = 3.4e38f, m2 = 3.4e38f, m3 = 3.4e38f;
        #pragma unroll
        for (int s = 0; s < NSAMP; s++) {
            float syv = sy[s];
            float sxv = sx[s];
            float dy  = __fsub_rn(fy, syv);
            float dy2 = __fmul_rn(dy, dy);   // reference: dy*dy as its own op
            float d;
            d = __fsub_rn(fx0, sxv); m0 = fminf(m0, __fadd_rn(dy2, __fmul_rn(d, d)));
            d = __fsub_rn(fx1, sxv); m1 = fminf(m1, __fadd_rn(dy2, __fmul_rn(d, d)));
            d = __fsub_rn(fx2, sxv); m2 = fminf(m2, __fadd_rn(dy2, __fmul_rn(d, d)));
            d = __fsub_rn(fx3, sxv); m3 = fminf(m3, __fadd_rn(dy2, __fmul_rn(d, d)));
        }
        // sqrt(min(d^2)) then compare < 2.0 — sqrt BEFORE compare, matching the
        // reference's boundary rounding. pow(x, 1.0) simplifies to x.
        const float maxd = sqrtf(2048.0f * 2048.0f + 2048.0f * 2048.0f);
        float d0 = sqrtf(m0), d1 = sqrtf(m1), d2s = sqrtf(m2), d3 = sqrtf(m3);
        v.x = (d0  < 2.0f) ? __fsub_rn(1.0f, __fdiv_rn(d0,  maxd)) : 0.0f;
        v.y = (d1  < 2.0f) ? __fsub_rn(1.0f, __fdiv_rn(d1,  maxd)) : 0.0f;
        v.z = (d2s < 2.0f) ? __fsub_rn(1.0f, __fdiv_rn(d2s, maxd)) : 0.0f;
        v.w = (d3  < 2.0f) ? __fsub_rn(1.0f, __fdiv_rn(d3,  maxd)) : 0.0f;
    }

    *reinterpret_cast<float4*>(out + (size_t)y * CANVAS_W + x) = v;
}

extern "C" void kernel_launch(void* const* d_in, const int* in_sizes, int n_in,
                              void* d_out, int out_size)
{
    const float* kp = (const float*)d_in[0];   // [3,2] normalized (y,x) control points
    float* out = (float*)d_out;                // [2048, 2048] float32

    dim3 block(32, 8);
    dim3 grid(CANVAS_W / TILE_W, CANVAS_H / TILE_H);  // (16, 256)
    path_raster_kernel<<<grid, block>>>(kp, out);
}